// round 1
// baseline (speedup 1.0000x reference)
#include <cuda_runtime.h>
#include <cstdint>

#define NUM_C 1000
#define DIM 128
#define MSZ 64
#define BATCH 64
#define LEN 512

// ---------------- device scratch (static, no runtime alloc) ----------------
__device__ float g_W [NUM_C * MSZ];        // softmax(Ek @ Mk^T) per q-row
__device__ float g_Ee[2 * NUM_C * DIM];    // sigmoid(Ev @ We + be) per x-row
__device__ float g_Ea[2 * NUM_C * DIM];    // tanh  (Ev @ Wa + ba) per x-row
__device__ float g_Kf[NUM_C * DIM];        // Ek @ Wf[128:256,:] per q-row
__device__ float g_read[BATCH * LEN * DIM];

// ---------------- packed f32x2 helpers ----------------
__device__ __forceinline__ void fma2(unsigned long long& d,
                                     unsigned long long a,
                                     unsigned long long b,
                                     unsigned long long c) {
    asm("fma.rn.f32x2 %0, %1, %2, %3;" : "=l"(d) : "l"(a), "l"(b), "l"(c));
}
__device__ __forceinline__ void mul2(unsigned long long& d,
                                     unsigned long long a,
                                     unsigned long long b) {
    asm("mul.rn.f32x2 %0, %1, %2;" : "=l"(d) : "l"(a), "l"(b));
}
__device__ __forceinline__ unsigned long long pack2(float lo, float hi) {
    unsigned long long r;
    asm("mov.b64 %0, {%1, %2};" : "=l"(r) : "f"(lo), "f"(hi));
    return r;
}
__device__ __forceinline__ float sum2(unsigned long long v) {
    float lo, hi;
    asm("mov.b64 {%0, %1}, %2;" : "=f"(lo), "=f"(hi) : "l"(v));
    return lo + hi;
}

// ============================================================================
// P1: per-x-row erase/add tables.  grid = 2000, block = 128
// ============================================================================
__global__ void k_pre_ea(const float* __restrict__ Ev,
                         const float* __restrict__ We,
                         const float* __restrict__ be,
                         const float* __restrict__ Wa,
                         const float* __restrict__ ba) {
    __shared__ float v[DIM];
    int row = blockIdx.x, d = threadIdx.x;
    v[d] = Ev[row * DIM + d];
    __syncthreads();
    float se = be[d], sa = ba[d];
#pragma unroll 16
    for (int j = 0; j < DIM; j++) {
        float vj = v[j];
        se = fmaf(vj, We[j * DIM + d], se);
        sa = fmaf(vj, Wa[j * DIM + d], sa);
    }
    g_Ee[row * DIM + d] = 1.0f / (1.0f + expf(-se));
    g_Ea[row * DIM + d] = tanhf(sa);
}

// ============================================================================
// P2: per-q-row softmax weights + Kf.  grid = 1000, block = 128
// ============================================================================
__global__ void k_pre_wkf(const float* __restrict__ Ek,
                          const float* __restrict__ Mk,
                          const float* __restrict__ Wf) {
    __shared__ float k[DIM];
    __shared__ float lg[MSZ];
    __shared__ float ex[MSZ];
    int row = blockIdx.x, t = threadIdx.x;
    k[t] = Ek[row * DIM + t];
    __syncthreads();

    // Kf column (all 128 threads)
    float kf = 0.0f;
#pragma unroll 16
    for (int j = 0; j < DIM; j++)
        kf = fmaf(k[j], Wf[(DIM + j) * DIM + t], kf);
    g_Kf[row * DIM + t] = kf;

    // logits (first 64 threads)
    if (t < MSZ) {
        float s = 0.0f;
#pragma unroll 16
        for (int j = 0; j < DIM; j++)
            s = fmaf(k[j], Mk[t * DIM + j], s);
        lg[t] = s;
    }
    __syncthreads();
    if (t < MSZ) {
        float mx = -1e30f;
#pragma unroll
        for (int m = 0; m < MSZ; m++) mx = fmaxf(mx, lg[m]);
        ex[t] = expf(lg[t] - mx);
    }
    __syncthreads();
    if (t < MSZ) {
        float den = 0.0f;
#pragma unroll
        for (int m = 0; m < MSZ; m++) den += ex[m];
        g_W[row * MSZ + t] = ex[t] / den;
    }
}

// ============================================================================
// S: sequential memory scan.  grid = (2, 64), block = 256
//    block handles batch b, 64 d-columns; thread = (d_local, m-group of 16)
//    Mv slice lives in 8 packed f32x2 registers per thread.
// ============================================================================
__global__ __launch_bounds__(256)
void k_scan(const int* __restrict__ q, const int* __restrict__ r,
            const float* __restrict__ Mv0) {
    int b = blockIdx.y;
    int dsplit = blockIdx.x;
    int tid = threadIdx.x;
    int dl = tid >> 2;        // 0..63
    int mg = tid & 3;         // 0..3
    int d = dsplit * 64 + dl;
    int m0 = mg * 16;

    unsigned long long Mv[8];
#pragma unroll
    for (int i = 0; i < 8; i++) {
        float lo = Mv0[(m0 + 2 * i) * DIM + d];
        float hi = Mv0[(m0 + 2 * i + 1) * DIM + d];
        Mv[i] = pack2(lo, hi);
    }

    __shared__ float sh_w[16][MSZ];
    __shared__ float sh_e[16][64];
    __shared__ float sh_a[16][64];

    const unsigned long long ONES = 0x3F8000003F800000ull;
    const int* qb = q + b * LEN;
    const int* rb = r + b * LEN;

    for (int c = 0; c < LEN / 16; c++) {
        int t0 = c * 16;
        __syncthreads();           // previous chunk fully consumed
        // stage w (16 steps x 64 slots) via q gather
        for (int idx = tid; idx < 1024; idx += 256) {
            int s = idx >> 6, m = idx & 63;
            int qv = qb[t0 + s];
            sh_w[s][m] = g_W[qv * MSZ + m];
        }
        // stage e/a for this block's d-range via x gather
        for (int idx = tid; idx < 1024; idx += 256) {
            int s = idx >> 6, dd = idx & 63;
            int xv = qb[t0 + s] + NUM_C * rb[t0 + s];
            int base = xv * DIM + dsplit * 64 + dd;
            sh_e[s][dd] = g_Ee[base];
            sh_a[s][dd] = g_Ea[base];
        }
        __syncthreads();

#pragma unroll 4
        for (int s = 0; s < 16; s++) {
            float e = sh_e[s][dl];
            float a = sh_a[s][dl];
            unsigned long long ne2 = pack2(-e, -e);
            unsigned long long a2  = pack2(a, a);
            unsigned long long rd = 0ull;
            const unsigned long long* wrow =
                (const unsigned long long*)(&sh_w[s][m0]);
#pragma unroll
            for (int i = 0; i < 8; i++) {
                unsigned long long w2 = wrow[i];
                unsigned long long c1, wa;
                fma2(rd, w2, Mv[i], rd);        // read += w * Mv (old)
                fma2(c1, ne2, w2, ONES);        // 1 - e*w
                mul2(wa, w2, a2);               // w * a
                fma2(Mv[i], Mv[i], c1, wa);     // Mv = Mv*(1-we) + wa
            }
            float rs = sum2(rd);
            rs += __shfl_xor_sync(0xFFFFFFFFu, rs, 1);
            rs += __shfl_xor_sync(0xFFFFFFFFu, rs, 2);
            if (mg == 0)
                g_read[(b * LEN + t0 + s) * DIM + d] = rs;
        }
    }
}

// ============================================================================
// F: f = tanh(read@Wf_r + Kf[q] + bf); p = sigmoid(f@Wp + bp)
//    grid = 1024 (32 tokens each), block = 128.  Wf_r column in registers.
// ============================================================================
__global__ __launch_bounds__(128)
void k_final(const int* __restrict__ q,
             const float* __restrict__ Wf,
             const float* __restrict__ bf,
             const float* __restrict__ Wp,
             const float* __restrict__ bp,
             float* __restrict__ out) {
    const int TT = 32;
    __shared__ float rs[TT][DIM];
    __shared__ float part[TT][4];
    int tid = threadIdx.x;
    int tok0 = blockIdx.x * TT;

    float wreg[DIM];
#pragma unroll
    for (int j = 0; j < DIM; j++) wreg[j] = Wf[j * DIM + tid];
    float bfv = bf[tid];
    float wpv = Wp[tid];
    float bpv = bp[0];

#pragma unroll
    for (int it = 0; it < TT; it++)
        rs[it][tid] = g_read[(tok0 + it) * DIM + tid];
    __syncthreads();

    int warp = tid >> 5, lane = tid & 31;
    for (int tt = 0; tt < TT; tt++) {
        int qv = q[tok0 + tt];
        float4 acc = {0.f, 0.f, 0.f, 0.f};
#pragma unroll
        for (int j = 0; j < DIM; j += 4) {
            float4 r4 = *(const float4*)&rs[tt][j];   // broadcast LDS.128
            acc.x = fmaf(r4.x, wreg[j],     acc.x);
            acc.y = fmaf(r4.y, wreg[j + 1], acc.y);
            acc.z = fmaf(r4.z, wreg[j + 2], acc.z);
            acc.w = fmaf(r4.w, wreg[j + 3], acc.w);
        }
        float f = tanhf(acc.x + acc.y + acc.z + acc.w +
                        g_Kf[qv * DIM + tid] + bfv);
        float contrib = f * wpv;
#pragma unroll
        for (int off = 16; off; off >>= 1)
            contrib += __shfl_xor_sync(0xFFFFFFFFu, contrib, off);
        if (lane == 0) part[tt][warp] = contrib;
    }
    __syncthreads();
    if (tid < TT) {
        float s = part[tid][0] + part[tid][1] + part[tid][2] + part[tid][3];
        out[tok0 + tid] = 1.0f / (1.0f + expf(-(s + bpv)));
    }
}

// ============================================================================
extern "C" void kernel_launch(void* const* d_in, const int* in_sizes, int n_in,
                              void* d_out, int out_size) {
    const int*   q   = (const int*)  d_in[0];
    const int*   r   = (const int*)  d_in[1];
    const float* Ek  = (const float*)d_in[2];
    const float* Ev  = (const float*)d_in[3];
    const float* Mk  = (const float*)d_in[4];
    const float* Mv0 = (const float*)d_in[5];
    const float* We  = (const float*)d_in[6];
    const float* be  = (const float*)d_in[7];
    const float* Wa  = (const float*)d_in[8];
    const float* ba  = (const float*)d_in[9];
    const float* Wf  = (const float*)d_in[10];
    const float* bf  = (const float*)d_in[11];
    const float* Wp  = (const float*)d_in[12];
    const float* bp  = (const float*)d_in[13];
    float* out = (float*)d_out;

    k_pre_ea <<<2 * NUM_C, DIM>>>(Ev, We, be, Wa, ba);
    k_pre_wkf<<<NUM_C, DIM>>>(Ek, Mk, Wf);
    dim3 gs(2, BATCH);
    k_scan   <<<gs, 256>>>(q, r, Mv0);
    k_final  <<<BATCH * LEN / 32, DIM>>>(q, Wf, bf, Wp, bp, out);
}

// round 3
// speedup vs baseline: 2.8466x; 2.8466x over previous
#include <cuda_runtime.h>
#include <cstdint>

#define NUM_C 1000
#define DIM 128
#define MSZ 64
#define BATCH 64
#define LEN 512

// ---------------- device scratch (static, no runtime alloc) ----------------
__device__ __align__(16) float g_W [NUM_C * MSZ];     // softmax(Ek@Mk^T) per q
__device__ __align__(16) float g_Ee[2 * NUM_C * DIM]; // sigmoid(Ev@We+be) per x
__device__ __align__(16) float g_Ea[2 * NUM_C * DIM]; // tanh(Ev@Wa+ba) per x
__device__ __align__(16) float g_Kf[NUM_C * DIM];     // Ek @ Wf[128:256,:]
__device__ __align__(16) float g_read[BATCH * LEN * DIM];

// ---------------- packed f32x2 helpers ----------------
__device__ __forceinline__ void fma2(unsigned long long& d,
                                     unsigned long long a,
                                     unsigned long long b,
                                     unsigned long long c) {
    asm("fma.rn.f32x2 %0, %1, %2, %3;" : "=l"(d) : "l"(a), "l"(b), "l"(c));
}
__device__ __forceinline__ unsigned long long pack2(float lo, float hi) {
    unsigned long long r;
    asm("mov.b64 %0, {%1, %2};" : "=l"(r) : "f"(lo), "f"(hi));
    return r;
}
__device__ __forceinline__ float sum2(unsigned long long v) {
    float lo, hi;
    asm("mov.b64 {%0, %1}, %2;" : "=f"(lo), "=f"(hi) : "l"(v));
    return lo + hi;
}

// ============================================================================
// P: fused precompute.  grid = 250, block = 128.
//    blocks [0,125):  erase/add tables, 16 Ev-rows each (weight reuse x16)
//    blocks [125,250): softmax weights + Kf, 8 Ek-rows each
// ============================================================================
__global__ __launch_bounds__(128)
void k_pre(const float* __restrict__ Ev,
           const float* __restrict__ We, const float* __restrict__ be,
           const float* __restrict__ Wa, const float* __restrict__ ba,
           const float* __restrict__ Ek,
           const float* __restrict__ Mk,
           const float* __restrict__ Wf) {
    __shared__ float buf[10112];   // 39.5 KB, reused by both branches
    int t = threadIdx.x;

    if (blockIdx.x < 125) {
        // ------- erase/add branch: rows row0..row0+15 -------
        float (*vrows)[DIM] = (float (*)[DIM])buf;  // [16][128]
        int row0 = blockIdx.x * 16;
#pragma unroll
        for (int i = 0; i < 16; i++)
            vrows[i][t] = Ev[(row0 + i) * DIM + t];
        __syncthreads();

        float ae[16], aa[16];
        float bev = be[t], bav = ba[t];
#pragma unroll
        for (int i = 0; i < 16; i++) { ae[i] = bev; aa[i] = bav; }
#pragma unroll 4
        for (int j = 0; j < DIM; j++) {
            float we = We[j * DIM + t];
            float wa = Wa[j * DIM + t];
#pragma unroll
            for (int i = 0; i < 16; i++) {
                float v = vrows[i][j];
                ae[i] = fmaf(v, we, ae[i]);
                aa[i] = fmaf(v, wa, aa[i]);
            }
        }
#pragma unroll
        for (int i = 0; i < 16; i++) {
            g_Ee[(row0 + i) * DIM + t] = 1.0f / (1.0f + expf(-ae[i]));
            g_Ea[(row0 + i) * DIM + t] = tanhf(aa[i]);
        }
    } else {
        // ------- w/Kf branch: rows row0..row0+7 -------
        float (*Mks)[129]  = (float (*)[129])buf;               // [64][129]
        float (*krows)[DIM] = (float (*)[DIM])(buf + 64 * 129); // [8][128]
        float (*lg)[MSZ]   = (float (*)[MSZ])(buf + 64 * 129 + 8 * DIM);
        int row0 = (blockIdx.x - 125) * 8;
#pragma unroll
        for (int i = 0; i < 8; i++)
            krows[i][t] = Ek[(row0 + i) * DIM + t];
#pragma unroll
        for (int i = 0; i < 64; i++) {
            int idx = t + i * 128;
            Mks[idx >> 7][idx & 127] = Mk[idx];
        }
        __syncthreads();

        // Kf columns (all 128 threads, 8 rows per weight load)
        float acc[8] = {0,0,0,0,0,0,0,0};
#pragma unroll 4
        for (int j = 0; j < DIM; j++) {
            float wf = Wf[(DIM + j) * DIM + t];
#pragma unroll
            for (int i = 0; i < 8; i++)
                acc[i] = fmaf(krows[i][j], wf, acc[i]);
        }
#pragma unroll
        for (int i = 0; i < 8; i++)
            g_Kf[(row0 + i) * DIM + t] = acc[i];

        // logits: thread t<64 owns memory slot t for all 8 rows
        if (t < MSZ) {
            float la[8] = {0,0,0,0,0,0,0,0};
#pragma unroll 4
            for (int j = 0; j < DIM; j++) {
                float mk = Mks[t][j];
#pragma unroll
                for (int i = 0; i < 8; i++)
                    la[i] = fmaf(krows[i][j], mk, la[i]);
            }
#pragma unroll
            for (int i = 0; i < 8; i++) lg[i][t] = la[i];
        }
        __syncthreads();

        // softmax: 16 threads per row, 4 slots each
        int row = t >> 4, l = t & 15;
        float v0 = lg[row][l],      v1 = lg[row][l + 16];
        float v2 = lg[row][l + 32], v3 = lg[row][l + 48];
        float mx = fmaxf(fmaxf(v0, v1), fmaxf(v2, v3));
#pragma unroll
        for (int off = 1; off < 16; off <<= 1)
            mx = fmaxf(mx, __shfl_xor_sync(0xFFFFFFFFu, mx, off));
        float e0 = expf(v0 - mx), e1 = expf(v1 - mx);
        float e2 = expf(v2 - mx), e3 = expf(v3 - mx);
        float s = e0 + e1 + e2 + e3;
#pragma unroll
        for (int off = 1; off < 16; off <<= 1)
            s += __shfl_xor_sync(0xFFFFFFFFu, s, off);
        float inv = 1.0f / s;
        float* wout = g_W + (row0 + row) * MSZ;
        wout[l]      = e0 * inv;
        wout[l + 16] = e1 * inv;
        wout[l + 32] = e2 * inv;
        wout[l + 48] = e3 * inv;
    }
}

// ============================================================================
// S: sequential memory scan.  grid = (2, 64), block = 256
//    3 packed FMA per element: Mv += w*(a - e*Mv);  read += w*Mv_old
//    Register-staged prefetch of next 16-step chunk overlaps compute.
// ============================================================================
__global__ __launch_bounds__(256)
void k_scan(const int* __restrict__ q, const int* __restrict__ r,
            const float* __restrict__ Mv0) {
    int b = blockIdx.y;
    int dsplit = blockIdx.x;
    int tid = threadIdx.x;
    int dl = tid >> 2;        // 0..63
    int mg = tid & 3;         // 0..3
    int d = dsplit * 64 + dl;
    int m0 = mg * 16;

    __shared__ int sq[LEN];
    __shared__ int sx[LEN];
    __shared__ __align__(16) float sh_w[16][MSZ];
    __shared__ float sh_e[16][64];
    __shared__ float sh_a[16][64];

    // preload q / x index rows
    {
        const int* qb = q + b * LEN;
        const int* rb = r + b * LEN;
        for (int i = tid; i < LEN; i += 256) {
            int qv = qb[i];
            sq[i] = qv;
            sx[i] = qv + NUM_C * rb[i];
        }
    }

    unsigned long long Mv[8];
#pragma unroll
    for (int i = 0; i < 8; i++) {
        float lo = Mv0[(m0 + 2 * i) * DIM + d];
        float hi = Mv0[(m0 + 2 * i + 1) * DIM + d];
        Mv[i] = pack2(lo, hi);
    }
    __syncthreads();

    // staging registers: 4 w, 4 e, 4 a per thread
    float rw[4], re[4], ra[4];
    int ws0[4], wm[4], es0[4], ed[4];
#pragma unroll
    for (int k = 0; k < 4; k++) {
        int idx = tid + k * 256;
        ws0[k] = idx >> 6; wm[k] = idx & 63;
        es0[k] = idx >> 6; ed[k] = (idx & 63) + dsplit * 64;
    }
    // prefetch chunk 0
#pragma unroll
    for (int k = 0; k < 4; k++) {
        rw[k] = g_W [sq[ws0[k]] * MSZ + wm[k]];
        re[k] = g_Ee[sx[es0[k]] * DIM + ed[k]];
        ra[k] = g_Ea[sx[es0[k]] * DIM + ed[k]];
    }

    for (int c = 0; c < LEN / 16; c++) {
        // commit staged regs to shared
#pragma unroll
        for (int k = 0; k < 4; k++) {
            sh_w[ws0[k]][wm[k]]      = rw[k];
            sh_e[es0[k]][ed[k] & 63] = re[k];
            sh_a[es0[k]][ed[k] & 63] = ra[k];
        }
        __syncthreads();

        // issue next chunk's gathers (latency hidden under compute)
        if (c < LEN / 16 - 1) {
            int t1 = (c + 1) * 16;
#pragma unroll
            for (int k = 0; k < 4; k++) {
                rw[k] = g_W [sq[t1 + ws0[k]] * MSZ + wm[k]];
                re[k] = g_Ee[sx[t1 + es0[k]] * DIM + ed[k]];
                ra[k] = g_Ea[sx[t1 + es0[k]] * DIM + ed[k]];
            }
        }

        int t0 = c * 16;
#pragma unroll 4
        for (int s = 0; s < 16; s++) {
            float e = sh_e[s][dl];
            float a = sh_a[s][dl];
            unsigned long long ne2 = pack2(-e, -e);
            unsigned long long a2  = pack2(a, a);
            unsigned long long rd = 0ull;
            const unsigned long long* wrow =
                (const unsigned long long*)(&sh_w[s][m0]);
#pragma unroll
            for (int i = 0; i < 8; i++) {
                unsigned long long w2 = wrow[i];
                unsigned long long tmp;
                fma2(rd, w2, Mv[i], rd);       // read += w * Mv_old
                fma2(tmp, ne2, Mv[i], a2);     // tmp = a - e*Mv
                fma2(Mv[i], w2, tmp, Mv[i]);   // Mv += w*tmp
            }
            float rs = sum2(rd);
            rs += __shfl_xor_sync(0xFFFFFFFFu, rs, 1);
            rs += __shfl_xor_sync(0xFFFFFFFFu, rs, 2);
            if (mg == 0)
                g_read[(b * LEN + t0 + s) * DIM + d] = rs;
        }
        __syncthreads();
    }
}

// ============================================================================
// F: tiled SGEMM  f = tanh(read@Wf_r + Kf[q] + bf); p = sigmoid(f@Wp + bp)
//    grid = 256 (128 tokens each), block = 256, 8x8 thread tile,
//    Wf_r resident in 64KB shared.
// ============================================================================
__global__ __launch_bounds__(256, 2)
void k_final(const int* __restrict__ q,
             const float* __restrict__ Wf,
             const float* __restrict__ bf,
             const float* __restrict__ Wp,
             const float* __restrict__ bp,
             float* __restrict__ out) {
    __shared__ float Wfs[DIM][DIM];       // 64 KB: [k][n]
    __shared__ float rds[128][20];        // read tile [token][k], padded
    __shared__ float part[128][17];       // per-token partial p sums

    int tid = threadIdx.x;
    int ty = tid >> 4, tx = tid & 15;     // 16x16 thread grid
    int tok0 = blockIdx.x * 128;

    // load Wf_r (rows 0..127) into shared, coalesced
#pragma unroll
    for (int i = 0; i < 16; i++) {
        int idx = (tid + i * 256) * 4;    // float4 index *4
        *(float4*)&Wfs[idx >> 7][idx & 127] = *(const float4*)&Wf[idx];
    }
    __syncthreads();

    float acc[8][8];
#pragma unroll
    for (int i = 0; i < 8; i++)
#pragma unroll
        for (int j = 0; j < 8; j++) acc[i][j] = 0.0f;

    for (int kt = 0; kt < 8; kt++) {
        // stage read tile: 128 tokens x 16 k
#pragma unroll
        for (int v = 0; v < 2; v++) {
            int f = tid * 2 + v;          // float4 id, 512 total
            int tok = f >> 2, dpos = (f & 3) * 4;
            *(float4*)&rds[tok][dpos] =
                *(const float4*)&g_read[(tok0 + tok) * DIM + kt * 16 + dpos];
        }
        __syncthreads();

#pragma unroll
        for (int kk = 0; kk < 16; kk++) {
            float av[8];
#pragma unroll
            for (int i = 0; i < 8; i++) av[i] = rds[ty * 8 + i][kk];
            float4 b0 = *(const float4*)&Wfs[kt * 16 + kk][tx * 8];
            float4 b1 = *(const float4*)&Wfs[kt * 16 + kk][tx * 8 + 4];
            float bv[8] = {b0.x, b0.y, b0.z, b0.w, b1.x, b1.y, b1.z, b1.w};
#pragma unroll
            for (int i = 0; i < 8; i++)
#pragma unroll
                for (int j = 0; j < 8; j++)
                    acc[i][j] = fmaf(av[i], bv[j], acc[i][j]);
        }
        __syncthreads();
    }

    // epilogue
    float4 bf0 = *(const float4*)&bf[tx * 8];
    float4 bf1 = *(const float4*)&bf[tx * 8 + 4];
    float bfv[8] = {bf0.x, bf0.y, bf0.z, bf0.w, bf1.x, bf1.y, bf1.z, bf1.w};
    float4 wp0 = *(const float4*)&Wp[tx * 8];
    float4 wp1 = *(const float4*)&Wp[tx * 8 + 4];
    float wpv[8] = {wp0.x, wp0.y, wp0.z, wp0.w, wp1.x, wp1.y, wp1.z, wp1.w};

    int qv[8];
#pragma unroll
    for (int i = 0; i < 8; i++) qv[i] = q[tok0 + ty * 8 + i];

#pragma unroll
    for (int i = 0; i < 8; i++) {
        const float* kf = g_Kf + qv[i] * DIM + tx * 8;
        float psum = 0.0f;
#pragma unroll
        for (int j = 0; j < 8; j++) {
            float f = tanhf(acc[i][j] + kf[j] + bfv[j]);
            psum = fmaf(f, wpv[j], psum);
        }
        part[ty * 8 + i][tx] = psum;
    }
    __syncthreads();

    if (tid < 128) {
        float s = 0.0f;
#pragma unroll
        for (int x = 0; x < 16; x++) s += part[tid][x];
        out[tok0 + tid] = 1.0f / (1.0f + expf(-(s + bp[0])));
    }
}

// ============================================================================
extern "C" void kernel_launch(void* const* d_in, const int* in_sizes, int n_in,
                              void* d_out, int out_size) {
    const int*   q   = (const int*)  d_in[0];
    const int*   r   = (const int*)  d_in[1];
    const float* Ek  = (const float*)d_in[2];
    const float* Ev  = (const float*)d_in[3];
    const float* Mk  = (const float*)d_in[4];
    const float* Mv0 = (const float*)d_in[5];
    const float* We  = (const float*)d_in[6];
    const float* be  = (const float*)d_in[7];
    const float* Wa  = (const float*)d_in[8];
    const float* ba  = (const float*)d_in[9];
    const float* Wf  = (const float*)d_in[10];
    const float* bf  = (const float*)d_in[11];
    const float* Wp  = (const float*)d_in[12];
    const float* bp  = (const float*)d_in[13];
    float* out = (float*)d_out;

    k_pre<<<250, 128>>>(Ev, We, be, Wa, ba, Ek, Mk, Wf);
    dim3 gs(2, BATCH);
    k_scan<<<gs, 256>>>(q, r, Mv0);
    k_final<<<BATCH * LEN / 32 / 4, 256>>>(q, Wf, bf, Wp, bp, out);
}